// round 1
// baseline (speedup 1.0000x reference)
#include <cuda_runtime.h>

// Problem constants (fixed shapes from setup_inputs).
#define INF   128     // input feature dim
#define HIDF  256     // hidden dim
#define OUTF  64      // output dim
#define N1C   100000  // n_dst0
#define N2C   25000   // n_dst1
#define E0C   1600000
#define E1C   400000

// ---------------- device scratch (no allocations allowed) ----------------
__device__ __align__(16) float g_An[(size_t)N1C * INF];    // seg-mean of x_neigh
__device__ __align__(16) float g_At[(size_t)N1C * INF];    // seg-mean of x_tar
__device__ __align__(16) float g_X1[(size_t)N1C * HIDF];   // layer-1 relu output
__device__ __align__(16) float g_Ag1[(size_t)N2C * HIDF];  // seg-mean of X1
__device__ int g_cnt0[N1C];
__device__ int g_off0[N1C + 1];
__device__ int g_cur0[N1C];
__device__ int g_es0[E0C];
__device__ int g_cnt1[N2C];
__device__ int g_off1[N2C + 1];
__device__ int g_cur1[N2C];
__device__ int g_es1[E1C];
__device__ __align__(16) float g_Wc[512 * HIDF];  // combined layer01 weights (4 x 128 x 256)
__device__ __align__(16) float g_W2[512 * OUTF];  // [Wl2; Wr2]
__device__ float g_bA[HIDF];                      // b0 @ Wl1   (conditional on cnt>0)
__device__ float g_bB[HIDF];                      // b0 @ Wr1 + b1

// ---------------- small kernels ----------------
__global__ void zero_counts_kernel() {
    int i = blockIdx.x * blockDim.x + threadIdx.x;
    if (i < N1C) g_cnt0[i] = 0;
    else if (i < N1C + N2C) g_cnt1[i - N1C] = 0;
}

// Precompute combined weights:
//  Wc rows [0,128)   = Wl0@Wl1   (multiplies A_n)
//  Wc rows [128,256) = Wr0@Wl1   (multiplies A_t)
//  Wc rows [256,384) = Wl0@Wr1   (multiplies x_neigh[:N1])
//  Wc rows [384,512) = Wr0@Wr1   (multiplies x_tar[:N1])
//  W2 = [Wl2; Wr2], bA = b0@Wl1, bB = b0@Wr1 + b1
__global__ void prep_weights_kernel(
    const float* __restrict__ Wl0, const float* __restrict__ Wr0,
    const float* __restrict__ b0,
    const float* __restrict__ Wl1, const float* __restrict__ Wr1,
    const float* __restrict__ b1,
    const float* __restrict__ Wl2, const float* __restrict__ Wr2) {
    int idx = blockIdx.x * blockDim.x + threadIdx.x;
    if (idx < 512 * 256) {
        int i = idx >> 8;        // 0..511 (stacked input-dim row)
        int j = idx & 255;       // 0..255 (hidden col)
        int blk = i >> 7;
        int il = i & 127;
        const float* M1 = (blk == 0 || blk == 2) ? Wl0 : Wr0;  // 128x256
        const float* M2 = (blk < 2) ? Wl1 : Wr1;               // 256x256
        float s = 0.f;
        #pragma unroll 8
        for (int k = 0; k < 256; k++) s = fmaf(M1[il * 256 + k], M2[k * 256 + j], s);
        g_Wc[idx] = s;
    } else if (idx < 512 * 256 + 512 * 64) {
        int r = idx - 512 * 256;
        int i = r >> 6, j = r & 63;
        g_W2[r] = (i < 256) ? Wl2[i * 64 + j] : Wr2[(i - 256) * 64 + j];
    } else if (idx < 512 * 256 + 512 * 64 + 256) {
        int j = idx - (512 * 256 + 512 * 64);
        float sa = 0.f, sb = 0.f;
        for (int k = 0; k < 256; k++) {
            sa = fmaf(b0[k], Wl1[k * 256 + j], sa);
            sb = fmaf(b0[k], Wr1[k * 256 + j], sb);
        }
        g_bA[j] = sa;
        g_bB[j] = sb + b1[j];
    }
}

__global__ void count0_kernel(const int* __restrict__ dst, int n) {
    int i = blockIdx.x * blockDim.x + threadIdx.x;
    if (i < n) atomicAdd(&g_cnt0[dst[i]], 1);
}
__global__ void count1_kernel(const int* __restrict__ dst, int n) {
    int i = blockIdx.x * blockDim.x + threadIdx.x;
    if (i < n) atomicAdd(&g_cnt1[dst[i]], 1);
}

// single-block exclusive scan (n <= ~100K), also initializes scatter cursors
__device__ __forceinline__ void scan_impl(const int* __restrict__ cnt,
                                          int* __restrict__ off,
                                          int* __restrict__ cur, int n) {
    __shared__ int part[1024];
    int t = threadIdx.x;
    int chunk = (n + 1023) >> 10;
    int beg = t * chunk;
    int end = beg + chunk;
    if (beg > n) beg = n;
    if (end > n) end = n;
    int s = 0;
    for (int i = beg; i < end; i++) s += cnt[i];
    part[t] = s;
    __syncthreads();
    for (int d = 1; d < 1024; d <<= 1) {
        int v = (t >= d) ? part[t - d] : 0;
        __syncthreads();
        part[t] += v;
        __syncthreads();
    }
    int run = part[t] - s;  // exclusive prefix of this thread's chunk
    for (int i = beg; i < end; i++) {
        off[i] = run;
        cur[i] = run;
        run += cnt[i];
    }
    if (t == 1023) off[n] = part[1023];
}
__global__ void scan0_kernel() { scan_impl(g_cnt0, g_off0, g_cur0, N1C); }
__global__ void scan1_kernel() { scan_impl(g_cnt1, g_off1, g_cur1, N2C); }

__global__ void scatter0_kernel(const int* __restrict__ src, const int* __restrict__ dst, int n) {
    int i = blockIdx.x * blockDim.x + threadIdx.x;
    if (i < n) {
        int p = atomicAdd(&g_cur0[dst[i]], 1);
        g_es0[p] = src[i];
    }
}
__global__ void scatter1_kernel(const int* __restrict__ src, const int* __restrict__ dst, int n) {
    int i = blockIdx.x * blockDim.x + threadIdx.x;
    if (i < n) {
        int p = atomicAdd(&g_cur1[dst[i]], 1);
        g_es1[p] = src[i];
    }
}

// one block per dst node; 256 threads: t<128 -> x_neigh feature, t>=128 -> x_tar feature
__global__ __launch_bounds__(256) void agg0_kernel(const float* __restrict__ xn,
                                                   const float* __restrict__ xt) {
    int d = blockIdx.x;
    int t = threadIdx.x;
    int b = g_off0[d], e = g_off0[d + 1];
    const float* base = (t < 128) ? xn : xt;
    int f = t & 127;
    float acc = 0.f;
    for (int i = b; i < e; i++) {
        int s = g_es0[i];
        acc += __ldg(&base[(size_t)s * INF + f]);
    }
    float inv = (e > b) ? 1.f / (float)(e - b) : 0.f;  // matches s/max(c,1): empty -> 0
    acc *= inv;
    if (t < 128) g_An[(size_t)d * INF + f] = acc;
    else         g_At[(size_t)d * INF + f] = acc;
}

__global__ __launch_bounds__(256) void agg1_kernel() {
    int d = blockIdx.x;
    int t = threadIdx.x;  // 256 features
    int b = g_off1[d], e = g_off1[d + 1];
    float acc = 0.f;
    for (int i = b; i < e; i++) {
        int s = g_es1[i];
        acc += __ldg(&g_X1[(size_t)s * HIDF + t]);
    }
    g_Ag1[(size_t)d * HIDF + t] = acc * ((e > b) ? 1.f / (float)(e - b) : 0.f);
}

// Fused layer-0+1 GEMM: X1 = relu([A_n|A_t|xn_t|xt_t] @ Wc + bias)
// M=100000, K=512, N=256. BM=BN=128, BK=8, 256 threads, 8x8 per thread.
__global__ __launch_bounds__(256) void gemm1_kernel(const float* __restrict__ xn,
                                                    const float* __restrict__ xt, int M) {
    __shared__ __align__(16) float As[8][128];
    __shared__ __align__(16) float Bs[8][128];
    int tid = threadIdx.x;
    int tx = tid & 15, ty = tid >> 4;
    int rowbase = blockIdx.x * 128;
    int colbase = blockIdx.y * 128;
    float acc[8][8] = {};
    int la_row = tid >> 1;
    int la_k = (tid & 1) << 2;
    int lb_row = tid >> 5;
    int lb_col = (tid & 31) << 2;
    int arow = rowbase + la_row;
    if (arow >= M) arow = M - 1;  // clamp (rows >= M never stored)
    const float* srcs[4] = {g_An, g_At, xn, xt};
    for (int ko = 0; ko < 512; ko += 8) {
        const float* A = srcs[ko >> 7];
        float4 av = *reinterpret_cast<const float4*>(A + (size_t)arow * INF + (ko & 127) + la_k);
        As[la_k + 0][la_row] = av.x;
        As[la_k + 1][la_row] = av.y;
        As[la_k + 2][la_row] = av.z;
        As[la_k + 3][la_row] = av.w;
        float4 bv = *reinterpret_cast<const float4*>(g_Wc + (ko + lb_row) * 256 + colbase + lb_col);
        *reinterpret_cast<float4*>(&Bs[lb_row][lb_col]) = bv;
        __syncthreads();
        #pragma unroll
        for (int kk = 0; kk < 8; kk++) {
            float4 a0 = *reinterpret_cast<const float4*>(&As[kk][ty * 8]);
            float4 a1 = *reinterpret_cast<const float4*>(&As[kk][ty * 8 + 4]);
            float4 b0 = *reinterpret_cast<const float4*>(&Bs[kk][tx * 8]);
            float4 b1 = *reinterpret_cast<const float4*>(&Bs[kk][tx * 8 + 4]);
            float a[8] = {a0.x, a0.y, a0.z, a0.w, a1.x, a1.y, a1.z, a1.w};
            float b[8] = {b0.x, b0.y, b0.z, b0.w, b1.x, b1.y, b1.z, b1.w};
            #pragma unroll
            for (int i = 0; i < 8; i++)
                #pragma unroll
                for (int j = 0; j < 8; j++)
                    acc[i][j] = fmaf(a[i], b[j], acc[i][j]);
        }
        __syncthreads();
    }
    #pragma unroll
    for (int i = 0; i < 8; i++) {
        int grow = rowbase + ty * 8 + i;
        if (grow < M) {
            int c = g_cnt0[grow];
            float* orow = g_X1 + (size_t)grow * HIDF + colbase + tx * 8;
            float4 o0, o1;
            float tmp[8];
            #pragma unroll
            for (int j = 0; j < 8; j++) {
                int col = colbase + tx * 8 + j;
                float v = acc[i][j] + g_bB[col] + (c > 0 ? g_bA[col] : 0.f);
                tmp[j] = fmaxf(v, 0.f);
            }
            o0.x = tmp[0]; o0.y = tmp[1]; o0.z = tmp[2]; o0.w = tmp[3];
            o1.x = tmp[4]; o1.y = tmp[5]; o1.z = tmp[6]; o1.w = tmp[7];
            *reinterpret_cast<float4*>(orow) = o0;
            *reinterpret_cast<float4*>(orow + 4) = o1;
        }
    }
}

// Layer-2 GEMM fused with log_softmax: out = logsoftmax([Ag1|X1[:N2]] @ [Wl2;Wr2] + b2)
// M=25000, K=512, N=64. BM=BN=64, BK=16, 256 threads, 4x4 per thread.
__global__ __launch_bounds__(256) void gemm2_kernel(const float* __restrict__ b2,
                                                    float* __restrict__ out, int M) {
    __shared__ __align__(16) float As[16][64];
    __shared__ __align__(16) float Bs[16][64];
    __shared__ float Cs[64][65];
    int tid = threadIdx.x;
    int tx = tid & 15, ty = tid >> 4;
    int rowbase = blockIdx.x * 64;
    float acc[4][4] = {};
    int la_row = tid >> 2;        // 0..63
    int la_k = (tid & 3) << 2;    // 0,4,8,12
    int lb_k = tid >> 4;          // 0..15
    int lb_col = (tid & 15) << 2;
    int arow = rowbase + la_row;
    if (arow >= M) arow = M - 1;
    for (int ko = 0; ko < 512; ko += 16) {
        const float* A = (ko < 256) ? (g_Ag1 + (size_t)arow * HIDF + ko)
                                    : (g_X1 + (size_t)arow * HIDF + (ko - 256));
        float4 av = *reinterpret_cast<const float4*>(A + la_k);
        As[la_k + 0][la_row] = av.x;
        As[la_k + 1][la_row] = av.y;
        As[la_k + 2][la_row] = av.z;
        As[la_k + 3][la_row] = av.w;
        float4 bv = *reinterpret_cast<const float4*>(g_W2 + (ko + lb_k) * 64 + lb_col);
        *reinterpret_cast<float4*>(&Bs[lb_k][lb_col]) = bv;
        __syncthreads();
        #pragma unroll
        for (int kk = 0; kk < 16; kk++) {
            float4 a = *reinterpret_cast<const float4*>(&As[kk][ty * 4]);
            float4 b = *reinterpret_cast<const float4*>(&Bs[kk][tx * 4]);
            float aa[4] = {a.x, a.y, a.z, a.w};
            float bb[4] = {b.x, b.y, b.z, b.w};
            #pragma unroll
            for (int i = 0; i < 4; i++)
                #pragma unroll
                for (int j = 0; j < 4; j++)
                    acc[i][j] = fmaf(aa[i], bb[j], acc[i][j]);
        }
        __syncthreads();
    }
    #pragma unroll
    for (int i = 0; i < 4; i++)
        #pragma unroll
        for (int j = 0; j < 4; j++)
            Cs[ty * 4 + i][tx * 4 + j] = acc[i][j] + b2[tx * 4 + j];
    __syncthreads();
    int w = tid >> 5, lane = tid & 31;
    for (int r8 = 0; r8 < 8; r8++) {
        int r = w * 8 + r8;
        float v0 = Cs[r][lane], v1 = Cs[r][lane + 32];
        float m = fmaxf(v0, v1);
        #pragma unroll
        for (int o = 16; o > 0; o >>= 1) m = fmaxf(m, __shfl_xor_sync(0xffffffffu, m, o));
        float se = expf(v0 - m) + expf(v1 - m);
        #pragma unroll
        for (int o = 16; o > 0; o >>= 1) se += __shfl_xor_sync(0xffffffffu, se, o);
        float lse = m + logf(se);
        int grow = rowbase + r;
        if (grow < M) {
            out[(size_t)grow * OUTF + lane] = v0 - lse;
            out[(size_t)grow * OUTF + lane + 32] = v1 - lse;
        }
    }
}

// ---------------- launch ----------------
extern "C" void kernel_launch(void* const* d_in, const int* in_sizes, int n_in,
                              void* d_out, int out_size) {
    const float* x_tar   = (const float*)d_in[0];
    const float* x_neigh = (const float*)d_in[1];
    const int* esrc0 = (const int*)d_in[2];
    const int* edst0 = (const int*)d_in[3];
    const int* esrc1 = (const int*)d_in[4];
    const int* edst1 = (const int*)d_in[5];
    const float* Wl0 = (const float*)d_in[8];
    const float* Wr0 = (const float*)d_in[9];
    const float* b0  = (const float*)d_in[10];
    const float* Wl1 = (const float*)d_in[11];
    const float* Wr1 = (const float*)d_in[12];
    const float* b1  = (const float*)d_in[13];
    const float* Wl2 = (const float*)d_in[14];
    const float* Wr2 = (const float*)d_in[15];
    const float* b2  = (const float*)d_in[16];
    int E0 = in_sizes[2];
    int E1 = in_sizes[4];
    int M1 = N1C;
    int M2 = out_size / OUTF;
    float* out = (float*)d_out;

    zero_counts_kernel<<<(N1C + N2C + 255) / 256, 256>>>();
    prep_weights_kernel<<<(512 * 256 + 512 * 64 + 256 + 255) / 256, 256>>>(
        Wl0, Wr0, b0, Wl1, Wr1, b1, Wl2, Wr2);

    count0_kernel<<<(E0 + 255) / 256, 256>>>(edst0, E0);
    scan0_kernel<<<1, 1024>>>();
    scatter0_kernel<<<(E0 + 255) / 256, 256>>>(esrc0, edst0, E0);
    agg0_kernel<<<N1C, 256>>>(x_neigh, x_tar);

    dim3 g1((M1 + 127) / 128, 2);
    gemm1_kernel<<<g1, 256>>>(x_neigh, x_tar, M1);

    count1_kernel<<<(E1 + 255) / 256, 256>>>(edst1, E1);
    scan1_kernel<<<1, 1024>>>();
    scatter1_kernel<<<(E1 + 255) / 256, 256>>>(esrc1, edst1, E1);
    agg1_kernel<<<N2C, 256>>>();

    gemm2_kernel<<<(M2 + 63) / 64, 256>>>(b2, out, M2);
}

// round 3
// speedup vs baseline: 1.9995x; 1.9995x over previous
#include <cuda_runtime.h>
#include <cuda_bf16.h>
#include <cstdint>

#define INF   128
#define HIDF  256
#define OUTF  64
#define N1C   100000
#define N2C   25000
#define E0C   1600000
#define E1C   400000

// ======================= PTX helpers (sm_103 baseline ISA only) =======================
__device__ __forceinline__ uint32_t smem_to_u32(const void* smem_ptr) {
    uint32_t addr;
    asm("{ .reg .u64 tmp; cvta.to.shared.u64 tmp, %1; cvt.u32.u64 %0, tmp; }"
        : "=r"(addr) : "l"(smem_ptr));
    return addr;
}
#define CP_ASYNC16(dst, src) \
    asm volatile("cp.async.cg.shared.global [%0], [%1], 16;" :: "r"(dst), "l"(src))
#define CP_COMMIT() asm volatile("cp.async.commit_group;" ::: "memory")
#define CP_WAIT(n)  asm volatile("cp.async.wait_group %0;" :: "n"(n) : "memory")
#define LDSM4(r, addr) \
    asm volatile("ldmatrix.sync.aligned.m8n8.x4.shared.b16 {%0,%1,%2,%3}, [%4];" \
        : "=r"((r)[0]), "=r"((r)[1]), "=r"((r)[2]), "=r"((r)[3]) : "r"(addr))
#define MMA16816(d, a, b) \
    asm volatile("mma.sync.aligned.m16n8k16.row.col.f32.bf16.bf16.f32 " \
        "{%0,%1,%2,%3}, {%4,%5,%6,%7}, {%8,%9}, {%0,%1,%2,%3};" \
        : "+f"((d)[0]), "+f"((d)[1]), "+f"((d)[2]), "+f"((d)[3]) \
        : "r"((a)[0]), "r"((a)[1]), "r"((a)[2]), "r"((a)[3]), \
          "r"((b)[0]), "r"((b)[1]))

__device__ __forceinline__ uint32_t pack2(float a, float b) {
    __nv_bfloat162 p = __floats2bfloat162_rn(a, b);
    return *reinterpret_cast<uint32_t*>(&p);
}
__device__ __forceinline__ float tobf(float x) {
    return __bfloat162float(__float2bfloat16_rn(x));
}

// ======================= device scratch =======================
__device__ __align__(16) float g_An[(size_t)N1C * INF];
__device__ __align__(16) float g_At[(size_t)N1C * INF];
__device__ __align__(16) float g_X1[(size_t)N1C * HIDF];
__device__ __align__(16) float g_Ag1[(size_t)N2C * HIDF];
__device__ int g_cnt0[N1C];
__device__ int g_off0[N1C + 1];
__device__ int g_cur0[N1C];
__device__ int g_es0[E0C];
__device__ int g_cnt1[N2C];
__device__ int g_off1[N2C + 1];
__device__ int g_cur1[N2C];
__device__ int g_es1[E1C];
__device__ int g_part0[256];
__device__ int g_part1[64];
__device__ __align__(128) __nv_bfloat16 g_Bhi[256 * 512];  // [N=256][K=512]
__device__ __align__(128) __nv_bfloat16 g_Blo[256 * 512];
__device__ __align__(16) float g_W2[512 * OUTF];
__device__ float g_bA[HIDF];
__device__ float g_bB[HIDF];

// ======================= small kernels =======================
__global__ void zero_counts_kernel() {
    int i = blockIdx.x * blockDim.x + threadIdx.x;
    if (i < N1C) g_cnt0[i] = 0;
    else if (i < N1C + N2C) g_cnt1[i - N1C] = 0;
}

// Combined weights: K index i in [0,512): blocks {An:Wl0Wl1, At:Wr0Wl1, xn:Wl0Wr1, xt:Wr0Wr1}
// Stored transposed as B[N=256][K=512] bf16 hi/lo. Also W2, bA, bB.
__global__ void prep_weights_kernel(
    const float* __restrict__ Wl0, const float* __restrict__ Wr0,
    const float* __restrict__ b0,
    const float* __restrict__ Wl1, const float* __restrict__ Wr1,
    const float* __restrict__ b1,
    const float* __restrict__ Wl2, const float* __restrict__ Wr2) {
    int idx = blockIdx.x * blockDim.x + threadIdx.x;
    if (idx < 512 * 256) {
        int i = idx >> 8;
        int j = idx & 255;
        int blk = i >> 7;
        int il = i & 127;
        const float* M1 = (blk == 0 || blk == 2) ? Wl0 : Wr0;
        const float* M2 = (blk < 2) ? Wl1 : Wr1;
        float s = 0.f;
        #pragma unroll 8
        for (int k = 0; k < 256; k++) s = fmaf(M1[il * 256 + k], M2[k * 256 + j], s);
        __nv_bfloat16 hi = __float2bfloat16_rn(s);
        __nv_bfloat16 lo = __float2bfloat16_rn(s - __bfloat162float(hi));
        g_Bhi[j * 512 + i] = hi;
        g_Blo[j * 512 + i] = lo;
    } else if (idx < 512 * 256 + 512 * 64) {
        int r = idx - 512 * 256;
        int i = r >> 6, j = r & 63;
        g_W2[r] = (i < 256) ? Wl2[i * 64 + j] : Wr2[(i - 256) * 64 + j];
    } else if (idx < 512 * 256 + 512 * 64 + 256) {
        int j = idx - (512 * 256 + 512 * 64);
        float sa = 0.f, sb = 0.f;
        for (int k = 0; k < 256; k++) {
            sa = fmaf(b0[k], Wl1[k * 256 + j], sa);
            sb = fmaf(b0[k], Wr1[k * 256 + j], sb);
        }
        g_bA[j] = sa;
        g_bB[j] = sb + b1[j];
    }
}

__global__ void count0_kernel(const int* __restrict__ dst, int n) {
    int i = blockIdx.x * blockDim.x + threadIdx.x;
    if (i < n) atomicAdd(&g_cnt0[dst[i]], 1);
}
__global__ void count1_kernel(const int* __restrict__ dst, int n) {
    int i = blockIdx.x * blockDim.x + threadIdx.x;
    if (i < n) atomicAdd(&g_cnt1[dst[i]], 1);
}

// -------- 3-phase parallel scan --------
__device__ __forceinline__ void scan_part_impl(const int* __restrict__ cnt,
                                               int* __restrict__ part, int n) {
    __shared__ int ws[8];
    int base = blockIdx.x * 512;
    int t = threadIdx.x;
    int i0 = base + t * 2;
    int s = 0;
    if (i0 < n) s += cnt[i0];
    if (i0 + 1 < n) s += cnt[i0 + 1];
    #pragma unroll
    for (int o = 16; o > 0; o >>= 1) s += __shfl_down_sync(0xffffffffu, s, o);
    if ((t & 31) == 0) ws[t >> 5] = s;
    __syncthreads();
    if (t == 0) {
        int tot = 0;
        #pragma unroll
        for (int i = 0; i < 8; i++) tot += ws[i];
        part[blockIdx.x] = tot;
    }
}
__device__ __forceinline__ void scan_top_impl(int* __restrict__ part, int nb) {
    __shared__ int ws[8];
    int t = threadIdx.x;
    int v = (t < nb) ? part[t] : 0;
    int lane = t & 31, w = t >> 5;
    int incl = v;
    #pragma unroll
    for (int o = 1; o < 32; o <<= 1) {
        int x = __shfl_up_sync(0xffffffffu, incl, o);
        if (lane >= o) incl += x;
    }
    if (lane == 31) ws[w] = incl;
    __syncthreads();
    if (t == 0) {
        int run = 0;
        #pragma unroll
        for (int i = 0; i < 8; i++) { int tm = ws[i]; ws[i] = run; run += tm; }
    }
    __syncthreads();
    if (t < nb) part[t] = incl - v + ws[w];
}
__device__ __forceinline__ void scan_final_impl(const int* __restrict__ cnt,
                                                const int* __restrict__ part,
                                                int* __restrict__ off,
                                                int* __restrict__ cur, int n) {
    __shared__ int ws[8];
    int base = blockIdx.x * 512;
    int t = threadIdx.x;
    int i0 = base + t * 2;
    int c0 = (i0 < n) ? cnt[i0] : 0;
    int c1 = (i0 + 1 < n) ? cnt[i0 + 1] : 0;
    int s = c0 + c1;
    int lane = t & 31, w = t >> 5;
    int incl = s;
    #pragma unroll
    for (int o = 1; o < 32; o <<= 1) {
        int x = __shfl_up_sync(0xffffffffu, incl, o);
        if (lane >= o) incl += x;
    }
    if (lane == 31) ws[w] = incl;
    __syncthreads();
    if (t == 0) {
        int run = 0;
        #pragma unroll
        for (int i = 0; i < 8; i++) { int tm = ws[i]; ws[i] = run; run += tm; }
    }
    __syncthreads();
    int excl = incl - s + ws[w] + part[blockIdx.x];
    if (i0 < n) { off[i0] = excl; cur[i0] = excl; }
    if (i0 + 1 < n) { off[i0 + 1] = excl + c0; cur[i0 + 1] = excl + c0; }
    if (i0 == n - 1) off[n] = excl + c0;
    else if (i0 + 1 == n - 1) off[n] = excl + c0 + c1;
}
__global__ void scanA_part()  { scan_part_impl(g_cnt0, g_part0, N1C); }
__global__ void scanA_top()   { scan_top_impl(g_part0, (N1C + 511) / 512); }
__global__ void scanA_final() { scan_final_impl(g_cnt0, g_part0, g_off0, g_cur0, N1C); }
__global__ void scanB_part()  { scan_part_impl(g_cnt1, g_part1, N2C); }
__global__ void scanB_top()   { scan_top_impl(g_part1, (N2C + 511) / 512); }
__global__ void scanB_final() { scan_final_impl(g_cnt1, g_part1, g_off1, g_cur1, N2C); }

__global__ void scatter0_kernel(const int* __restrict__ src, const int* __restrict__ dst, int n) {
    int i = blockIdx.x * blockDim.x + threadIdx.x;
    if (i < n) {
        int p = atomicAdd(&g_cur0[dst[i]], 1);
        g_es0[p] = src[i];
    }
}
__global__ void scatter1_kernel(const int* __restrict__ src, const int* __restrict__ dst, int n) {
    int i = blockIdx.x * blockDim.x + threadIdx.x;
    if (i < n) {
        int p = atomicAdd(&g_cur1[dst[i]], 1);
        g_es1[p] = src[i];
    }
}

// warp-pair per dst: even warp -> x_neigh, odd warp -> x_tar, float4 per lane
__global__ __launch_bounds__(256) void agg0_kernel(const float* __restrict__ xn,
                                                   const float* __restrict__ xt) {
    int w = threadIdx.x >> 5, lane = threadIdx.x & 31;
    int d = blockIdx.x * 4 + (w >> 1);
    if (d >= N1C) return;
    const float* src = (w & 1) ? xt : xn;
    float* dstp = (w & 1) ? g_At : g_An;
    int b = g_off0[d], e = g_off0[d + 1];
    float4 acc = make_float4(0.f, 0.f, 0.f, 0.f);
    int i = b;
    for (; i + 1 < e; i += 2) {
        int s0 = g_es0[i], s1 = g_es0[i + 1];
        float4 v0 = __ldg(reinterpret_cast<const float4*>(src + (size_t)s0 * INF) + lane);
        float4 v1 = __ldg(reinterpret_cast<const float4*>(src + (size_t)s1 * INF) + lane);
        acc.x += v0.x + v1.x; acc.y += v0.y + v1.y;
        acc.z += v0.z + v1.z; acc.w += v0.w + v1.w;
    }
    if (i < e) {
        int s0 = g_es0[i];
        float4 v0 = __ldg(reinterpret_cast<const float4*>(src + (size_t)s0 * INF) + lane);
        acc.x += v0.x; acc.y += v0.y; acc.z += v0.z; acc.w += v0.w;
    }
    float inv = (e > b) ? 1.f / (float)(e - b) : 0.f;
    acc.x *= inv; acc.y *= inv; acc.z *= inv; acc.w *= inv;
    reinterpret_cast<float4*>(dstp + (size_t)d * INF)[lane] = acc;
}

__global__ __launch_bounds__(256) void agg1_kernel() {
    int w = threadIdx.x >> 5, lane = threadIdx.x & 31;
    int d = blockIdx.x * 4 + (w >> 1);
    if (d >= N2C) return;
    int colb = (w & 1) * 128;
    int b = g_off1[d], e = g_off1[d + 1];
    float4 acc = make_float4(0.f, 0.f, 0.f, 0.f);
    int i = b;
    for (; i + 1 < e; i += 2) {
        int s0 = g_es1[i], s1 = g_es1[i + 1];
        float4 v0 = __ldg(reinterpret_cast<const float4*>(g_X1 + (size_t)s0 * HIDF + colb) + lane);
        float4 v1 = __ldg(reinterpret_cast<const float4*>(g_X1 + (size_t)s1 * HIDF + colb) + lane);
        acc.x += v0.x + v1.x; acc.y += v0.y + v1.y;
        acc.z += v0.z + v1.z; acc.w += v0.w + v1.w;
    }
    if (i < e) {
        int s0 = g_es1[i];
        float4 v0 = __ldg(reinterpret_cast<const float4*>(g_X1 + (size_t)s0 * HIDF + colb) + lane);
        acc.x += v0.x; acc.y += v0.y; acc.z += v0.z; acc.w += v0.w;
    }
    float inv = (e > b) ? 1.f / (float)(e - b) : 0.f;
    acc.x *= inv; acc.y *= inv; acc.z *= inv; acc.w *= inv;
    reinterpret_cast<float4*>(g_Ag1 + (size_t)d * HIDF + colb)[lane] = acc;
}

// ======================= HMMA fused layer-0+1 GEMM =======================
// X1 = relu([A_n|A_t|xn_t|xt_t](K=512) @ B(512x256) + bias), split-bf16 x3 via mma.sync.
// CTA: 128 rows x 128 cols, 8 warps (warp tile 32x64). BK=32, double-buffered SMEM.
// SMEM stage (40KB): As_hi[128][40]b16 | As_lo | Bs_hi[128][40]b16 | Bs_lo (rows padded
// to 80B so ldmatrix 8-lane phases hit distinct 16B banks: row*5 mod 8 is a full cycle).
#define G1_STAGE   40960
#define G1_AHI     0
#define G1_ALO     10240
#define G1_BHI     20480
#define G1_BLO     30720
#define GEMM1_SMEM (2 * G1_STAGE)

__global__ __launch_bounds__(256, 1) void gemm1_mma_kernel(const float* __restrict__ xn,
                                                           const float* __restrict__ xt,
                                                           int M) {
    extern __shared__ char smem[];
    const uint32_t smem_u = smem_to_u32(smem);
    int tid = threadIdx.x;
    int lane = tid & 31, wid = tid >> 5;
    int warp_m = wid & 3, warp_n = wid >> 2;
    int rowbase = blockIdx.y * 128;
    int colbase = blockIdx.x * 128;

    const float* srcs[4] = {g_An, g_At, xn, xt};

    // A loader coords: 4 passes of 32 rows; each row 32 floats = 8 float4
    int arow_l = tid >> 3;       // 0..31
    int acol4 = tid & 7;         // float4 index (k-offset acol4*4)
    // B loader coords: per precision 128 n x 64B; thread covers 32B
    int bn = tid >> 1;           // 0..127
    int bko = (tid & 1) * 32;    // byte offset in 64B k-window

    // ldmatrix lane addresses (offsets within a stage)
    uint32_t aoff = (uint32_t)((warp_m * 32 + (lane & 15)) * 80 + ((lane >> 4) * 16));
    uint32_t boff = (uint32_t)((warp_n * 64 + (lane & 7) + ((lane >> 4) << 3)) * 80 +
                               (((lane >> 3) & 1) * 16));

    float acc[2][8][4] = {};
    float4 pf[4];

    auto ldgA = [&](int s) {
        const float* src = srcs[s >> 2];
        int kb = (s & 3) * 32 + acol4 * 4;
        #pragma unroll
        for (int p = 0; p < 4; p++) {
            int gr = rowbase + arow_l + p * 32;
            if (gr >= M) gr = M - 1;
            pf[p] = __ldg(reinterpret_cast<const float4*>(src + (size_t)gr * INF + kb));
        }
    };
    auto stsA = [&](int par) {
        char* st = smem + par * G1_STAGE;
        #pragma unroll
        for (int p = 0; p < 4; p++) {
            int row = arow_l + p * 32;
            float4 v = pf[p];
            uint2 hi, lo;
            hi.x = pack2(v.x, v.y);
            hi.y = pack2(v.z, v.w);
            lo.x = pack2(v.x - tobf(v.x), v.y - tobf(v.y));
            lo.y = pack2(v.z - tobf(v.z), v.w - tobf(v.w));
            *reinterpret_cast<uint2*>(st + G1_AHI + row * 80 + acol4 * 8) = hi;
            *reinterpret_cast<uint2*>(st + G1_ALO + row * 80 + acol4 * 8) = lo;
        }
    };
    auto cpB = [&](int s, int par) {
        size_t srow = (size_t)(colbase + bn) * 1024 + (size_t)s * 64 + bko;
        const char* sh = reinterpret_cast<const char*>(g_Bhi) + srow;
        const char* sl = reinterpret_cast<const char*>(g_Blo) + srow;
        uint32_t dh = smem_u + par * G1_STAGE + G1_BHI + bn * 80 + bko;
        uint32_t dl = smem_u + par * G1_STAGE + G1_BLO + bn * 80 + bko;
        CP_ASYNC16(dh, sh);
        CP_ASYNC16(dh + 16, sh + 16);
        CP_ASYNC16(dl, sl);
        CP_ASYNC16(dl + 16, sl + 16);
        CP_COMMIT();
    };

    ldgA(0);
    cpB(0, 0);

    for (int s = 0; s < 16; s++) {
        int par = s & 1;
        stsA(par);
        if (s < 15) {
            ldgA(s + 1);
            cpB(s + 1, 1 - par);
            CP_WAIT(1);
        } else {
            CP_WAIT(0);
        }
        __syncthreads();

        uint32_t sb = smem_u + par * G1_STAGE;
        #pragma unroll
        for (int k16 = 0; k16 < 2; k16++) {
            uint32_t ah[8], al[8];
            LDSM4(ah,     sb + G1_AHI + aoff + k16 * 32);
            LDSM4(ah + 4, sb + G1_AHI + aoff + 16 * 80 + k16 * 32);
            LDSM4(al,     sb + G1_ALO + aoff + k16 * 32);
            LDSM4(al + 4, sb + G1_ALO + aoff + 16 * 80 + k16 * 32);
            uint32_t bh[16], bl[16];
            #pragma unroll
            for (int nt2 = 0; nt2 < 4; nt2++)
                LDSM4(bh + nt2 * 4, sb + G1_BHI + boff + nt2 * 1280 + k16 * 32);
            #pragma unroll
            for (int nt2 = 0; nt2 < 4; nt2++)
                LDSM4(bl + nt2 * 4, sb + G1_BLO + boff + nt2 * 1280 + k16 * 32);
            #pragma unroll
            for (int mt = 0; mt < 2; mt++) {
                #pragma unroll
                for (int nt = 0; nt < 8; nt++) {
                    MMA16816(acc[mt][nt], ah + mt * 4, bh + nt * 2);
                    MMA16816(acc[mt][nt], ah + mt * 4, bl + nt * 2);
                    MMA16816(acc[mt][nt], al + mt * 4, bh + nt * 2);
                }
            }
        }
        __syncthreads();
    }

    // epilogue: bias (+conditional bA) + relu, direct STG (32B sectors per 8-row group)
    int gid = lane >> 2, tig = lane & 3;
    #pragma unroll
    for (int nt = 0; nt < 8; nt++) {
        int col = colbase + warp_n * 64 + nt * 8 + tig * 2;
        float bb0 = g_bB[col], bb1 = g_bB[col + 1];
        float ba0 = g_bA[col], ba1 = g_bA[col + 1];
        #pragma unroll
        for (int mt = 0; mt < 2; mt++) {
            int row0 = rowbase + warp_m * 32 + mt * 16 + gid;
            if (row0 < M) {
                bool c = g_cnt0[row0] > 0;
                float2 r;
                r.x = fmaxf(acc[mt][nt][0] + bb0 + (c ? ba0 : 0.f), 0.f);
                r.y = fmaxf(acc[mt][nt][1] + bb1 + (c ? ba1 : 0.f), 0.f);
                *reinterpret_cast<float2*>(&g_X1[(size_t)row0 * HIDF + col]) = r;
            }
            int row1 = row0 + 8;
            if (row1 < M) {
                bool c = g_cnt0[row1] > 0;
                float2 r;
                r.x = fmaxf(acc[mt][nt][2] + bb0 + (c ? ba0 : 0.f), 0.f);
                r.y = fmaxf(acc[mt][nt][3] + bb1 + (c ? ba1 : 0.f), 0.f);
                *reinterpret_cast<float2*>(&g_X1[(size_t)row1 * HIDF + col]) = r;
            }
        }
    }
}

// ======================= layer-2 GEMM + log_softmax =======================
__global__ __launch_bounds__(256) void gemm2_kernel(const float* __restrict__ b2,
                                                    float* __restrict__ out, int M) {
    __shared__ __align__(16) float As[16][64];
    __shared__ __align__(16) float Bs[16][64];
    __shared__ float Cs[64][65];
    int tid = threadIdx.x;
    int tx = tid & 15, ty = tid >> 4;
    int rowbase = blockIdx.x * 64;
    float acc[4][4] = {};
    int la_row = tid >> 2;
    int la_k = (tid & 3) << 2;
    int lb_k = tid >> 4;
    int lb_col = (tid & 15) << 2;
    int arow = rowbase + la_row;
    if (arow >= M) arow = M - 1;
    for (int ko = 0; ko < 512; ko += 16) {
        const float* A = (ko < 256) ? (g_Ag1 + (size_t)arow * HIDF + ko)
                                    : (g_X1 + (size_t)arow * HIDF + (ko - 256));
        float4 av = *reinterpret_cast<const float4*>(A + la_k);
        As[la_k + 0][la_row] = av.x;
        As[la_k + 1][la_row] = av.y;
        As[la_k + 2][la_row] = av.z;
        As[la_k + 3][la_row] = av.w;
        float4 bv = *reinterpret_cast<const float4*>(g_W2 + (ko + lb_k) * 64 + lb_col);
        *reinterpret_cast<float4*>(&Bs[lb_k][lb_col]) = bv;
        __syncthreads();
        #pragma unroll
        for (int kk = 0; kk < 16; kk++) {
            float4 a = *reinterpret_cast<const float4*>(&As[kk][ty * 4]);
            float4 b = *reinterpret_cast<const float4*>(&Bs[kk][tx * 4]);
            float aa[4] = {a.x, a.y, a.z, a.w};
            float bb[4] = {b.x, b.y, b.z, b.w};
            #pragma unroll
            for (int i = 0; i < 4; i++)
                #pragma unroll
                for (int j = 0; j < 4; j++)
                    acc[i][j] = fmaf(aa[i], bb[j], acc[i][j]);
        }
        __syncthreads();
    }
    #pragma unroll
    for (int i = 0; i < 4; i++)
        #pragma unroll
        for (int j = 0; j < 4; j++)
            Cs[ty * 4 + i][tx * 4 + j] = acc[i][j] + b2[tx * 4 + j];
    __syncthreads();
    int w = tid >> 5, lane = tid & 31;
    for (int r8 = 0; r8 < 8; r8++) {
        int r = w * 8 + r8;
        float v0 = Cs[r][lane], v1 = Cs[r][lane + 32];
        float m = fmaxf(v0, v1);
        #pragma unroll
        for (int o = 16; o > 0; o >>= 1) m = fmaxf(m, __shfl_xor_sync(0xffffffffu, m, o));
        float se = expf(v0 - m) + expf(v1 - m);
        #pragma unroll
        for (int o = 16; o > 0; o >>= 1) se += __shfl_xor_sync(0xffffffffu, se, o);
        float lse = m + logf(se);
        int grow = rowbase + r;
        if (grow < M) {
            out[(size_t)grow * OUTF + lane] = v0 - lse;
            out[(size_t)grow * OUTF + lane + 32] = v1 - lse;
        }
    }
}

// ======================= launch =======================
extern "C" void kernel_launch(void* const* d_in, const int* in_sizes, int n_in,
                              void* d_out, int out_size) {
    const float* x_tar   = (const float*)d_in[0];
    const float* x_neigh = (const float*)d_in[1];
    const int* esrc0 = (const int*)d_in[2];
    const int* edst0 = (const int*)d_in[3];
    const int* esrc1 = (const int*)d_in[4];
    const int* edst1 = (const int*)d_in[5];
    const float* Wl0 = (const float*)d_in[8];
    const float* Wr0 = (const float*)d_in[9];
    const float* b0  = (const float*)d_in[10];
    const float* Wl1 = (const float*)d_in[11];
    const float* Wr1 = (const float*)d_in[12];
    const float* b1  = (const float*)d_in[13];
    const float* Wl2 = (const float*)d_in[14];
    const float* Wr2 = (const float*)d_in[15];
    const float* b2  = (const float*)d_in[16];
    int E0 = in_sizes[2];
    int E1 = in_sizes[4];
    int M1 = N1C;
    int M2 = out_size / OUTF;
    float* out = (float*)d_out;

    cudaFuncSetAttribute(gemm1_mma_kernel, cudaFuncAttributeMaxDynamicSharedMemorySize,
                         GEMM1_SMEM);

    zero_counts_kernel<<<(N1C + N2C + 255) / 256, 256>>>();
    prep_weights_kernel<<<(512 * 256 + 512 * 64 + 256 + 255) / 256, 256>>>(
        Wl0, Wr0, b0, Wl1, Wr1, b1, Wl2, Wr2);

    count0_kernel<<<(E0 + 255) / 256, 256>>>(edst0, E0);
    scanA_part<<<(N1C + 511) / 512, 256>>>();
    scanA_top<<<1, 256>>>();
    scanA_final<<<(N1C + 511) / 512, 256>>>();
    scatter0_kernel<<<(E0 + 255) / 256, 256>>>(esrc0, edst0, E0);
    agg0_kernel<<<(N1C + 3) / 4, 256>>>(x_neigh, x_tar);

    dim3 g1(2, (M1 + 127) / 128);
    gemm1_mma_kernel<<<g1, 256, GEMM1_SMEM>>>(x_neigh, x_tar, M1);

    count1_kernel<<<(E1 + 255) / 256, 256>>>(edst1, E1);
    scanB_part<<<(N2C + 511) / 512, 256>>>();
    scanB_top<<<1, 256>>>();
    scanB_final<<<(N2C + 511) / 512, 256>>>();
    scatter1_kernel<<<(E1 + 255) / 256, 256>>>(esrc1, edst1, E1);
    agg1_kernel<<<(N2C + 3) / 4, 256>>>();

    gemm2_kernel<<<(M2 + 63) / 64, 256>>>(b2, out, M2);
}